// round 15
// baseline (speedup 1.0000x reference)
#include <cuda_runtime.h>
#include <cuda_bf16.h>
#include <cstdint>

#define Bb   2
#define Cc   64
#define Nn   2304
#define Hh   4
#define Dh   16
#define BH   (Bb*Hh)
#define MLP  256

// flash-mma tiling
#define QT    64            // queries per block (4 warps x 16 rows)
#define KT    64            // keys per smem tile
#define KSPL  4             // key splits
#define KPB   (Nn/KSPL)     // 576 keys per block
#define NTIL  (KPB/KT)      // 9 tiles
#define SKQ   24            // row stride in bf16 (48B = 3*16B, ldmatrix-friendly)

typedef unsigned long long u64;

// ---------------- scratch (device globals; no allocation) ----------------
__device__ float    g_xt [Bb*Nn*Cc];       // x transposed (b, n, c)
__device__ uint32_t g_qb [BH*Nn*8];        // Q bf16x2, pre-scaled by 0.25*log2e
__device__ uint32_t g_kb [BH*Nn*8];        // K bf16x2
__device__ uint32_t g_vb [BH*Nn*8];        // V bf16x2
__device__ float    g_secl[BH*256];        // channel-attn logits (atomic accum)
__device__ float    g_po [KSPL*BH*Nn*16];  // unnormalized attention partials
__device__ float    g_pl [KSPL*BH*Nn];     // partial row sums

// ---------------- helpers ----------------
__device__ __forceinline__ float ex2a(float x) {
    float r; asm("ex2.approx.f32 %0, %1;" : "=f"(r) : "f"(x)); return r;
}
__device__ __forceinline__ uint32_t cvt_bf2(float hi, float lo) {
    uint32_t r; asm("cvt.rn.bf16x2.f32 %0, %1, %2;" : "=r"(r) : "f"(hi), "f"(lo)); return r;
}
__device__ __forceinline__ void mma16816(float d[4],
    uint32_t a0, uint32_t a1, uint32_t a2, uint32_t a3,
    uint32_t b0, uint32_t b1)
{
    asm volatile("mma.sync.aligned.m16n8k16.row.col.f32.bf16.bf16.f32 "
        "{%0,%1,%2,%3}, {%4,%5,%6,%7}, {%8,%9}, {%0,%1,%2,%3};"
        : "+f"(d[0]), "+f"(d[1]), "+f"(d[2]), "+f"(d[3])
        : "r"(a0), "r"(a1), "r"(a2), "r"(a3), "r"(b0), "r"(b1));
}
__device__ __forceinline__ void ldsm_x4(uint32_t& r0, uint32_t& r1, uint32_t& r2, uint32_t& r3, uint32_t addr) {
    asm volatile("ldmatrix.sync.aligned.m8n8.x4.shared.b16 {%0,%1,%2,%3}, [%4];"
        : "=r"(r0), "=r"(r1), "=r"(r2), "=r"(r3) : "r"(addr));
}
__device__ __forceinline__ void ldsm_x4t(uint32_t& r0, uint32_t& r1, uint32_t& r2, uint32_t& r3, uint32_t addr) {
    asm volatile("ldmatrix.sync.aligned.m8n8.x4.trans.shared.b16 {%0,%1,%2,%3}, [%4];"
        : "=r"(r0), "=r"(r1), "=r"(r2), "=r"(r3) : "r"(addr));
}
__device__ __forceinline__ u64 fma2(u64 a, u64 b, u64 c) {
    u64 d; asm("fma.rn.f32x2 %0, %1, %2, %3;" : "=l"(d) : "l"(a), "l"(b), "l"(c)); return d;
}
__device__ __forceinline__ float2 unpk(u64 v) {
    float2 r; asm("mov.b64 {%0,%1}, %2;" : "=f"(r.x), "=f"(r.y) : "l"(v)); return r;
}
__device__ __forceinline__ u64 pk(float lo, float hi) {
    u64 v; asm("mov.b64 %0, {%1,%2};" : "=l"(v) : "f"(lo), "f"(hi)); return v;
}
__device__ __forceinline__ uint32_t smem_u32(const void* p) {
    return (uint32_t)__cvta_generic_to_shared(p);
}

// ---------------- K1: transpose + LN + 4 projections + bf16 QKV + secm partials ----------------
// 8 rows, 128 thr. Half h2 = t>>6 owns rows 4*h2..4*h2+3.
__global__ __launch_bounds__(128) void k_ln_proj(
    const float* __restrict__ x, const float* __restrict__ y,
    const float* __restrict__ g, const float* __restrict__ be,
    const float* __restrict__ wsa1, const float* __restrict__ wsa2,
    const float* __restrict__ wse1, const float* __restrict__ wse2)
{
    const int t = threadIdx.x;
    const int c = t & 63, h2 = t >> 6;
    const int row0 = blockIdx.x * 8;
    const int b = row0 / Nn;
    const int n0 = row0 - b*Nn;
    __shared__ u64 sxnp[4][64], synp[4][64];
    __shared__ u64 sx1p[4][64], sx2p[4][64];
    __shared__ float sred[4][16];

    float xv[4], yv[4];
#pragma unroll
    for (int k = 0; k < 4; k++) {
        int nn = n0 + 4*h2 + k;
        xv[k] = x[((size_t)b*Cc + c)*Nn + nn];
        yv[k] = y[((size_t)b*Cc + c)*Nn + nn];
        g_xt[(size_t)(row0 + 4*h2 + k)*Cc + c] = xv[k];
    }
    const int wid = t >> 5, lane = t & 31;
#pragma unroll
    for (int k = 0; k < 4; k++) {
        float a = xv[k], a2 = a*a, bb = yv[k], b2v = bb*bb;
#pragma unroll
        for (int o = 16; o > 0; o >>= 1) {
            a   += __shfl_xor_sync(0xffffffffu, a,   o);
            a2  += __shfl_xor_sync(0xffffffffu, a2,  o);
            bb  += __shfl_xor_sync(0xffffffffu, bb,  o);
            b2v += __shfl_xor_sync(0xffffffffu, b2v, o);
        }
        if (lane == 0) {
            sred[wid][k*4+0] = a;  sred[wid][k*4+1] = a2;
            sred[wid][k*4+2] = bb; sred[wid][k*4+3] = b2v;
        }
    }
    __syncthreads();
    const float gt = g[c], bet = be[c];
    float xnv[4], ynv[4];
    const int w0i = 2*h2, w1i = 2*h2 + 1;
#pragma unroll
    for (int k = 0; k < 4; k++) {
        float sx  = sred[w0i][k*4+0] + sred[w1i][k*4+0];
        float sx2 = sred[w0i][k*4+1] + sred[w1i][k*4+1];
        float sy  = sred[w0i][k*4+2] + sred[w1i][k*4+2];
        float sy2 = sred[w0i][k*4+3] + sred[w1i][k*4+3];
        float mx = sx*(1.f/64.f), vx = sx2*(1.f/64.f) - mx*mx;
        float my = sy*(1.f/64.f), vy = sy2*(1.f/64.f) - my*my;
        float rx = rsqrtf(vx + 1e-5f), ry = rsqrtf(vy + 1e-5f);
        xnv[k] = (xv[k]-mx)*rx*gt + bet;
        ynv[k] = (yv[k]-my)*ry*gt + bet;
    }
    sxnp[2*h2  ][c] = pk(xnv[0], xnv[1]);
    sxnp[2*h2+1][c] = pk(xnv[2], xnv[3]);
    synp[2*h2  ][c] = pk(ynv[0], ynv[1]);
    synp[2*h2+1][c] = pk(ynv[2], ynv[3]);
    __syncthreads();

    u64 a1[2] = {0,0}, a2a[2] = {0,0}, a3[2] = {0,0}, a4[2] = {0,0};
#pragma unroll 4
    for (int c2 = 0; c2 < 64; c2++) {
        float w1v = wsa1[c2*64+c], w2v = wsa2[c2*64+c];
        float w3v = wse1[c2*64+c], w4v = wse2[c2*64+c];
        u64 w1p = pk(w1v, w1v), w2p = pk(w2v, w2v);
        u64 w3p = pk(w3v, w3v), w4p = pk(w4v, w4v);
#pragma unroll
        for (int pi = 0; pi < 2; pi++) {
            u64 yc = synp[2*h2+pi][c2], xc = sxnp[2*h2+pi][c2];
            a1[pi]  = fma2(yc, w1p, a1[pi]);
            a2a[pi] = fma2(yc, w2p, a2a[pi]);
            a3[pi]  = fma2(xc, w3p, a3[pi]);
            a4[pi]  = fma2(xc, w4p, a4[pi]);
        }
    }
    const int h = c >> 4, d = c & 15;
    const int bhh = b*Hh + h;
    const float SCq = 0.25f * 1.4426950408889634f;
#pragma unroll
    for (int pi = 0; pi < 2; pi++) {
        const int n = n0 + 4*h2 + 2*pi;
        float2 u1 = unpk(a1[pi]);   // Q rows n, n+1
        float2 u2 = unpk(a2a[pi]);  // K
        float2 u3 = unpk(a3[pi]);   // V (x1)

        // pack bf16 across d with partner lane (d even <- own, d odd from c^1)
        float qx = u1.x * SCq, qy = u1.y * SCq;
        float pqx = __shfl_xor_sync(0xffffffffu, qx,   1);
        float pqy = __shfl_xor_sync(0xffffffffu, qy,   1);
        float pkx = __shfl_xor_sync(0xffffffffu, u2.x, 1);
        float pky = __shfl_xor_sync(0xffffffffu, u2.y, 1);
        float pvx = __shfl_xor_sync(0xffffffffu, u3.x, 1);
        float pvy = __shfl_xor_sync(0xffffffffu, u3.y, 1);
        if ((c & 1) == 0) {
            size_t r0 = ((size_t)bhh*Nn + n)*8 + (d >> 1);
            size_t r1 = r0 + 8;
            g_qb[r0] = cvt_bf2(pqx, qx);
            g_qb[r1] = cvt_bf2(pqy, qy);
            g_kb[r0] = cvt_bf2(pkx, u2.x);
            g_kb[r1] = cvt_bf2(pky, u2.y);
            g_vb[r0] = cvt_bf2(pvx, u3.x);
            g_vb[r1] = cvt_bf2(pvy, u3.y);
        }
    }

    // ---- channel-attn logit partials: sum over the 8 rows, atomic into g_secl
    sx1p[2*h2  ][c] = a3[0];  sx1p[2*h2+1][c] = a3[1];
    sx2p[2*h2  ][c] = a4[0];  sx2p[2*h2+1][c] = a4[1];
    __syncthreads();
#pragma unroll
    for (int e = 0; e < 8; e++) {
        int idx = t + 128*e;
        int hh = idx >> 8, ii = (idx >> 4) & 15, jj = idx & 15;
        u64 acc = 0ull;
#pragma unroll
        for (int p = 0; p < 4; p++)
            acc = fma2(sx1p[p][hh*16+ii], sx2p[p][hh*16+jj], acc);
        float2 u = unpk(acc);
        atomicAdd(&g_secl[(b*Hh + hh)*256 + ii*16 + jj], u.x + u.y);
    }
}

// ---------------- K3: flash attention, bf16 mma + ldmatrix, double-buffered ----------------
__global__ __launch_bounds__(128) void k_flash_mma()
{
    const int qt = blockIdx.x, bh = blockIdx.y, ks = blockIdx.z;
    const int t = threadIdx.x, wid = t >> 5, lane = t & 31;
    const int g = lane >> 2, tg = lane & 3;
    const int m = lane >> 3, r8 = lane & 7;

    __shared__ __align__(16) __nv_bfloat16 sQ [QT*SKQ];
    __shared__ __align__(16) __nv_bfloat16 sK [2][KT*SKQ];
    __shared__ __align__(16) __nv_bfloat16 sV [2][KT*SKQ];

    const uint4* __restrict__ Qb4 = ((const uint4*)g_qb) + (size_t)bh*Nn*2;
    const uint4* __restrict__ Kb4 = ((const uint4*)g_kb) + (size_t)bh*Nn*2;
    const uint4* __restrict__ Vb4 = ((const uint4*)g_vb) + (size_t)bh*Nn*2;

    // Q tile: 64 rows x 32B = 128 uint4, one per thread
    {
        uint4 v = Qb4[(size_t)qt*128 + t];
        *(uint4*)(sQ + (t>>1)*SKQ + (t&1)*8) = v;
    }
    // preload tile 0
    {
        const int key0 = ks*KPB;
        uint4 kv = Kb4[(size_t)key0*2 + t];
        uint4 vv = Vb4[(size_t)key0*2 + t];
        *(uint4*)(sK[0] + (t>>1)*SKQ + (t&1)*8) = kv;
        *(uint4*)(sV[0] + (t>>1)*SKQ + (t&1)*8) = vv;
    }
    __syncthreads();

    const int qr = wid * 16;
    uint32_t qa0 = *(const uint32_t*)(sQ + (qr+g  )*SKQ + 2*tg);
    uint32_t qa1 = *(const uint32_t*)(sQ + (qr+g+8)*SKQ + 2*tg);
    uint32_t qa2 = *(const uint32_t*)(sQ + (qr+g  )*SKQ + 2*tg + 8);
    uint32_t qa3 = *(const uint32_t*)(sQ + (qr+g+8)*SKQ + 2*tg + 8);

    const uint32_t offK = (uint32_t)(((((m>>1)&1)*8 + r8)*SKQ + (m&1)*8) * 2);
    const uint32_t offV = (uint32_t)((((m&1)*8 + r8)*SKQ + ((m>>1)&1)*8) * 2);
    const uint32_t kb0 = smem_u32(sK[0]), kb1 = smem_u32(sK[1]);
    const uint32_t vb0 = smem_u32(sV[0]), vb1 = smem_u32(sV[1]);

    float o[2][4] = {{0,0,0,0},{0,0,0,0}};
    float lsum_lo = 0.f, lsum_hi = 0.f;

    for (int kt = 0; kt < NTIL; kt++) {
        const int cur = kt & 1;
        const bool more = (kt + 1 < NTIL);

        uint4 kreg, vreg;
        if (more) {
            const int key0 = ks*KPB + (kt+1)*KT;
            kreg = Kb4[(size_t)key0*2 + t];
            vreg = Vb4[(size_t)key0*2 + t];
        }

        const uint32_t kbase = (cur ? kb1 : kb0) + offK;
        const uint32_t vbase = (cur ? vb1 : vb0) + offV;

        float s[8][4];
        uint32_t p[8][2];
#pragma unroll
        for (int kg = 0; kg < 4; kg++) {
            uint32_t b0, b1, b2, b3;
            ldsm_x4(b0, b1, b2, b3, kbase + kg*(16*SKQ*2));
            s[2*kg][0] = s[2*kg][1] = s[2*kg][2] = s[2*kg][3] = 0.f;
            s[2*kg+1][0] = s[2*kg+1][1] = s[2*kg+1][2] = s[2*kg+1][3] = 0.f;
            mma16816(s[2*kg],   qa0, qa1, qa2, qa3, b0, b1);
            mma16816(s[2*kg+1], qa0, qa1, qa2, qa3, b2, b3);
        }
        // Q pre-scaled by 0.25*log2(e) -> exp is a bare ex2
#pragma unroll
        for (int n = 0; n < 8; n++) {
            float e0 = ex2a(s[n][0]), e1 = ex2a(s[n][1]);
            float e2 = ex2a(s[n][2]), e3 = ex2a(s[n][3]);
            lsum_lo += e0 + e1;  lsum_hi += e2 + e3;
            p[n][0] = cvt_bf2(e1, e0);
            p[n][1] = cvt_bf2(e3, e2);
        }
#pragma unroll
        for (int kk = 0; kk < 4; kk++) {
            uint32_t v0, v1, v2, v3;
            ldsm_x4t(v0, v1, v2, v3, vbase + kk*(16*SKQ*2));
            mma16816(o[0], p[2*kk][0], p[2*kk][1], p[2*kk+1][0], p[2*kk+1][1], v0, v1);
            mma16816(o[1], p[2*kk][0], p[2*kk][1], p[2*kk+1][0], p[2*kk+1][1], v2, v3);
        }

        if (more) {
            const int nxt = cur ^ 1;
            *(uint4*)(sK[nxt] + (t>>1)*SKQ + (t&1)*8) = kreg;
            *(uint4*)(sV[nxt] + (t>>1)*SKQ + (t&1)*8) = vreg;
            __syncthreads();
        }
    }

    lsum_lo += __shfl_xor_sync(0xffffffffu, lsum_lo, 1);
    lsum_lo += __shfl_xor_sync(0xffffffffu, lsum_lo, 2);
    lsum_hi += __shfl_xor_sync(0xffffffffu, lsum_hi, 1);
    lsum_hi += __shfl_xor_sync(0xffffffffu, lsum_hi, 2);

    const int q_lo = qt*QT + qr + g;
    const int q_hi = q_lo + 8;
    float* po = g_po + ((size_t)(ks*BH + bh)*Nn)*16;
#pragma unroll
    for (int n = 0; n < 2; n++) {
        *(float2*)&po[(size_t)q_lo*16 + n*8 + 2*tg] = make_float2(o[n][0], o[n][1]);
        *(float2*)&po[(size_t)q_hi*16 + n*8 + 2*tg] = make_float2(o[n][2], o[n][3]);
    }
    if (tg == 0) {
        g_pl[(size_t)(ks*BH + bh)*Nn + q_lo] = lsum_lo;
        g_pl[(size_t)(ks*BH + bh)*Nn + q_hi] = lsum_hi;
    }
}

// ---------------- K4: secm softmax + combine + epilogue + out-proj + LN2 + MLP ----------------
__device__ __forceinline__ float leaky(float h) { return h > 0.f ? h : 0.01f * h; }

__global__ __launch_bounds__(128) void k_tail(
    const float* __restrict__ wout, const float* __restrict__ bout,
    const float* __restrict__ g2,   const float* __restrict__ be2,
    const float* __restrict__ w1,   const float* __restrict__ b1,
    const float* __restrict__ w2,   const float* __restrict__ b2,
    float* __restrict__ out)
{
    const int t = threadIdx.x;
    const int c = t & 63, h2 = t >> 6;
    const int row0 = blockIdx.x * 8;
    const int b = row0 / Nn;
    const int n0 = row0 - b*Nn;
    const int h = c >> 4, d = c & 15;
    const int bh = b*Hh + h;

    __shared__ float ssec[4][256];
    __shared__ float sq[8][64];
    __shared__ float sinvl[8][4];
    __shared__ u64 sop[4][64];
    __shared__ u64 snp[4][64];
    __shared__ u64 shp[4][256];
    __shared__ float sred[4][8];

    const float SCL = 0.25f / 144.0f;
    const float INVQ = 2.7725887222397812f;   // 4*ln2 — undoes Q pre-scale
#pragma unroll
    for (int k = 0; k < 8; k++) {
        int idx = k*128 + t;
        ssec[idx >> 8][idx & 255] = g_secl[(b*Hh + (idx >> 8))*256 + (idx & 255)];
    }
#pragma unroll
    for (int k = 0; k < 4; k++) {
        int n = n0 + 4*h2 + k;
        uint32_t qw = g_qb[((size_t)bh*Nn + n)*8 + (d >> 1)];
        __nv_bfloat162 q2 = *reinterpret_cast<__nv_bfloat162*>(&qw);
        float qv = (d & 1) ? __bfloat162float(__high2bfloat16(q2))
                           : __bfloat162float(__low2bfloat16(q2));
        sq[4*h2 + k][c] = qv * INVQ;
    }
    if (t < 32) {
        int r = t >> 2, hh = t & 3;
        float l = 0.f;
#pragma unroll
        for (int ks = 0; ks < KSPL; ks++)
            l += g_pl[(size_t)(ks*BH + b*Hh + hh)*Nn + n0 + r];
        sinvl[r][hh] = 1.0f / l;
    }
    __syncthreads();
    if (t < 64) {
        int hh = t >> 4, ii = t & 15;
        float* row = &ssec[hh][ii*16];
        float rm = -1e30f;
#pragma unroll
        for (int j = 0; j < 16; j++) rm = fmaxf(rm, row[j]*SCL);
        float rs = 0.f;
        float ev[16];
#pragma unroll
        for (int j = 0; j < 16; j++) { ev[j] = __expf(row[j]*SCL - rm); rs += ev[j]; }
        float inv = 1.0f / rs;
#pragma unroll
        for (int j = 0; j < 16; j++) row[j] = ev[j] * inv;
    }
    __syncthreads();

    float soval[4];
#pragma unroll
    for (int k = 0; k < 4; k++) {
        int r = 4*h2 + k;
        float pv = 0.f;
#pragma unroll
        for (int ks = 0; ks < KSPL; ks++)
            pv += g_po[((size_t)(ks*BH + bh)*Nn + n0 + r)*16 + d];
        float o2 = 0.f;
#pragma unroll
        for (int i = 0; i < 16; i++)
            o2 = fmaf(sq[r][h*16 + i], ssec[h][i*16 + d], o2);
        soval[k] = pv * sinvl[r][h] * o2;
    }
    sop[2*h2  ][c] = pk(soval[0], soval[1]);
    sop[2*h2+1][c] = pk(soval[2], soval[3]);
    __syncthreads();

    u64 ac[2] = {0ull, 0ull};
#pragma unroll 4
    for (int c2 = 0; c2 < 64; c2++) {
        float w = wout[c2*64 + c];
        u64 ww = pk(w, w);
        ac[0] = fma2(ww, sop[2*h2  ][c2], ac[0]);
        ac[1] = fma2(ww, sop[2*h2+1][c2], ac[1]);
    }
    const float bo = bout[c];
    float x2v[4];
#pragma unroll
    for (int pi = 0; pi < 2; pi++) {
        float2 u = unpk(ac[pi]);
        x2v[2*pi]   = g_xt[(size_t)(row0 + 4*h2 + 2*pi    )*64 + c] + u.x + bo;
        x2v[2*pi+1] = g_xt[(size_t)(row0 + 4*h2 + 2*pi + 1)*64 + c] + u.y + bo;
    }

    const int wid = t >> 5, lane = t & 31;
#pragma unroll
    for (int k = 0; k < 4; k++) {
        float a = x2v[k], a2 = a*a;
#pragma unroll
        for (int o = 16; o > 0; o >>= 1) {
            a  += __shfl_xor_sync(0xffffffffu, a,  o);
            a2 += __shfl_xor_sync(0xffffffffu, a2, o);
        }
        if (lane == 0) { sred[wid][k*2] = a; sred[wid][k*2+1] = a2; }
    }
    __syncthreads();
    const float g2t = g2[c], be2t = be2[c];
    const int wA = 2*h2, wB = 2*h2 + 1;
    float snv[4];
#pragma unroll
    for (int k = 0; k < 4; k++) {
        float sxx = sred[wA][k*2]   + sred[wB][k*2];
        float sq2 = sred[wA][k*2+1] + sred[wB][k*2+1];
        float mm = sxx*(1.f/64.f), vv = sq2*(1.f/64.f) - mm*mm;
        snv[k] = (x2v[k]-mm)*rsqrtf(vv + 1e-5f)*g2t + be2t;
    }
    snp[2*h2  ][c] = pk(snv[0], snv[1]);
    snp[2*h2+1][c] = pk(snv[2], snv[3]);
    __syncthreads();

    u64 hh1[2][4];
#pragma unroll
    for (int kk = 0; kk < 2; kk++) {
        float bb = b1[c + 64*(h2 + 2*kk)];
#pragma unroll
        for (int p = 0; p < 4; p++) hh1[kk][p] = pk(bb, bb);
    }
#pragma unroll 2
    for (int c2 = 0; c2 < 64; c2++) {
        u64 xp[4];
#pragma unroll
        for (int p = 0; p < 4; p++) xp[p] = snp[p][c2];
#pragma unroll
        for (int kk = 0; kk < 2; kk++) {
            float w = w1[c2*256 + c + 64*(h2 + 2*kk)];
            u64 ww = pk(w, w);
#pragma unroll
            for (int p = 0; p < 4; p++)
                hh1[kk][p] = fma2(ww, xp[p], hh1[kk][p]);
        }
    }
#pragma unroll
    for (int kk = 0; kk < 2; kk++) {
#pragma unroll
        for (int p = 0; p < 4; p++) {
            float2 u = unpk(hh1[kk][p]);
            shp[p][c + 64*(h2 + 2*kk)] = pk(leaky(u.x), leaky(u.y));
        }
    }
    __syncthreads();

    u64 f[2] = {0ull, 0ull};
#pragma unroll 4
    for (int j = 0; j < 256; j++) {
        float w = w2[j*64 + c];
        u64 ww = pk(w, w);
        f[0] = fma2(ww, shp[2*h2  ][j], f[0]);
        f[1] = fma2(ww, shp[2*h2+1][j], f[1]);
    }
    const float b2t = b2[c];
#pragma unroll
    for (int pi = 0; pi < 2; pi++) {
        float2 u = unpk(f[pi]);
        float2 st = make_float2(x2v[2*pi] + u.x + b2t, x2v[2*pi+1] + u.y + b2t);
        *(float2*)&out[((size_t)b*Cc + c)*Nn + n0 + 4*h2 + 2*pi] = st;
    }
}

// ---------------- launch ----------------
extern "C" void kernel_launch(void* const* d_in, const int* in_sizes, int n_in,
                              void* d_out, int out_size)
{
    (void)in_sizes; (void)n_in; (void)out_size;
    const float* x    = (const float*)d_in[0];
    const float* y    = (const float*)d_in[1];
    const float* ln1g = (const float*)d_in[2];
    const float* ln1b = (const float*)d_in[3];
    const float* wsa1 = (const float*)d_in[4];
    const float* wsa2 = (const float*)d_in[5];
    const float* wse1 = (const float*)d_in[6];
    const float* wse2 = (const float*)d_in[7];
    const float* wout = (const float*)d_in[8];
    const float* bout = (const float*)d_in[9];
    const float* ln2g = (const float*)d_in[10];
    const float* ln2b = (const float*)d_in[11];
    const float* w1   = (const float*)d_in[12];
    const float* b1   = (const float*)d_in[13];
    const float* w2   = (const float*)d_in[14];
    const float* b2   = (const float*)d_in[15];
    float* out = (float*)d_out;

    void* secl_ptr = nullptr;
    cudaGetSymbolAddress(&secl_ptr, g_secl);
    cudaMemsetAsync(secl_ptr, 0, BH*256*sizeof(float));

    k_ln_proj<<<Bb*Nn/8, 128>>>(x, y, ln1g, ln1b, wsa1, wsa2, wse1, wse2);
    dim3 gfl(Nn/QT, BH, KSPL);
    k_flash_mma<<<gfl, 128>>>();
    k_tail<<<Bb*Nn/8, 128>>>(wout, bout, ln2g, ln2b, w1, b1, w2, b2, out);
}

// round 16
// speedup vs baseline: 1.0354x; 1.0354x over previous
#include <cuda_runtime.h>
#include <cuda_bf16.h>
#include <cstdint>

#define Bb   2
#define Cc   64
#define Nn   2304
#define Hh   4
#define Dh   16
#define BH   (Bb*Hh)
#define MLP  256

// flash-mma tiling
#define QT    128           // queries per block (8 warps x 16 rows)
#define KT    64            // keys per smem tile
#define KSPL  4             // key splits
#define KPB   (Nn/KSPL)     // 576 keys per block
#define NTIL  (KPB/KT)      // 9 tiles
#define SKQ   24            // row stride in bf16 (48B = 3*16B, ldmatrix-friendly)

typedef unsigned long long u64;

// ---------------- scratch (device globals; no allocation) ----------------
__device__ float    g_xt [Bb*Nn*Cc];       // x transposed (b, n, c)
__device__ float    g_y1 [BH*Nn*Dh];       // Q float (for tail epilogue)
__device__ uint32_t g_qb [BH*Nn*8];        // Q bf16x2, pre-scaled by 0.25*log2e
__device__ uint32_t g_kb [BH*Nn*8];        // K bf16x2
__device__ uint32_t g_vb [BH*Nn*8];        // V bf16x2
__device__ float    g_secl[BH*256];        // channel-attn logits (atomic accum)
__device__ float    g_po [KSPL*BH*Nn*16];  // unnormalized attention partials
__device__ float    g_pl [KSPL*BH*Nn];     // partial row sums

// ---------------- helpers ----------------
__device__ __forceinline__ float ex2a(float x) {
    float r; asm("ex2.approx.f32 %0, %1;" : "=f"(r) : "f"(x)); return r;
}
__device__ __forceinline__ uint32_t cvt_bf2(float hi, float lo) {
    uint32_t r; asm("cvt.rn.bf16x2.f32 %0, %1, %2;" : "=r"(r) : "f"(hi), "f"(lo)); return r;
}
__device__ __forceinline__ void mma16816(float d[4],
    uint32_t a0, uint32_t a1, uint32_t a2, uint32_t a3,
    uint32_t b0, uint32_t b1)
{
    asm volatile("mma.sync.aligned.m16n8k16.row.col.f32.bf16.bf16.f32 "
        "{%0,%1,%2,%3}, {%4,%5,%6,%7}, {%8,%9}, {%0,%1,%2,%3};"
        : "+f"(d[0]), "+f"(d[1]), "+f"(d[2]), "+f"(d[3])
        : "r"(a0), "r"(a1), "r"(a2), "r"(a3), "r"(b0), "r"(b1));
}
__device__ __forceinline__ void ldsm_x4(uint32_t& r0, uint32_t& r1, uint32_t& r2, uint32_t& r3, uint32_t addr) {
    asm volatile("ldmatrix.sync.aligned.m8n8.x4.shared.b16 {%0,%1,%2,%3}, [%4];"
        : "=r"(r0), "=r"(r1), "=r"(r2), "=r"(r3) : "r"(addr));
}
__device__ __forceinline__ void ldsm_x4t(uint32_t& r0, uint32_t& r1, uint32_t& r2, uint32_t& r3, uint32_t addr) {
    asm volatile("ldmatrix.sync.aligned.m8n8.x4.trans.shared.b16 {%0,%1,%2,%3}, [%4];"
        : "=r"(r0), "=r"(r1), "=r"(r2), "=r"(r3) : "r"(addr));
}
__device__ __forceinline__ u64 fma2(u64 a, u64 b, u64 c) {
    u64 d; asm("fma.rn.f32x2 %0, %1, %2, %3;" : "=l"(d) : "l"(a), "l"(b), "l"(c)); return d;
}
__device__ __forceinline__ float2 unpk(u64 v) {
    float2 r; asm("mov.b64 {%0,%1}, %2;" : "=f"(r.x), "=f"(r.y) : "l"(v)); return r;
}
__device__ __forceinline__ u64 pk(float lo, float hi) {
    u64 v; asm("mov.b64 %0, {%1,%2};" : "=l"(v) : "f"(lo), "f"(hi)); return v;
}
__device__ __forceinline__ uint32_t smem_u32(const void* p) {
    return (uint32_t)__cvta_generic_to_shared(p);
}

// ---------------- K1: transpose + LN + 4 projections + bf16 QKV + secm partials ----------------
// 8 rows, 128 thr. Half h2 = t>>6 owns rows 4*h2..4*h2+3.  (exact R13)
__global__ __launch_bounds__(128) void k_ln_proj(
    const float* __restrict__ x, const float* __restrict__ y,
    const float* __restrict__ g, const float* __restrict__ be,
    const float* __restrict__ wsa1, const float* __restrict__ wsa2,
    const float* __restrict__ wse1, const float* __restrict__ wse2)
{
    const int t = threadIdx.x;
    const int c = t & 63, h2 = t >> 6;
    const int row0 = blockIdx.x * 8;
    const int b = row0 / Nn;
    const int n0 = row0 - b*Nn;
    __shared__ u64 sxnp[4][64], synp[4][64];
    __shared__ u64 sx1p[4][64], sx2p[4][64];
    __shared__ float sred[4][16];

    float xv[4], yv[4];
#pragma unroll
    for (int k = 0; k < 4; k++) {
        int nn = n0 + 4*h2 + k;
        xv[k] = x[((size_t)b*Cc + c)*Nn + nn];
        yv[k] = y[((size_t)b*Cc + c)*Nn + nn];
        g_xt[(size_t)(row0 + 4*h2 + k)*Cc + c] = xv[k];
    }
    const int wid = t >> 5, lane = t & 31;
#pragma unroll
    for (int k = 0; k < 4; k++) {
        float a = xv[k], a2 = a*a, bb = yv[k], b2v = bb*bb;
#pragma unroll
        for (int o = 16; o > 0; o >>= 1) {
            a   += __shfl_xor_sync(0xffffffffu, a,   o);
            a2  += __shfl_xor_sync(0xffffffffu, a2,  o);
            bb  += __shfl_xor_sync(0xffffffffu, bb,  o);
            b2v += __shfl_xor_sync(0xffffffffu, b2v, o);
        }
        if (lane == 0) {
            sred[wid][k*4+0] = a;  sred[wid][k*4+1] = a2;
            sred[wid][k*4+2] = bb; sred[wid][k*4+3] = b2v;
        }
    }
    __syncthreads();
    const float gt = g[c], bet = be[c];
    float xnv[4], ynv[4];
    const int w0i = 2*h2, w1i = 2*h2 + 1;
#pragma unroll
    for (int k = 0; k < 4; k++) {
        float sx  = sred[w0i][k*4+0] + sred[w1i][k*4+0];
        float sx2 = sred[w0i][k*4+1] + sred[w1i][k*4+1];
        float sy  = sred[w0i][k*4+2] + sred[w1i][k*4+2];
        float sy2 = sred[w0i][k*4+3] + sred[w1i][k*4+3];
        float mx = sx*(1.f/64.f), vx = sx2*(1.f/64.f) - mx*mx;
        float my = sy*(1.f/64.f), vy = sy2*(1.f/64.f) - my*my;
        float rx = rsqrtf(vx + 1e-5f), ry = rsqrtf(vy + 1e-5f);
        xnv[k] = (xv[k]-mx)*rx*gt + bet;
        ynv[k] = (yv[k]-my)*ry*gt + bet;
    }
    sxnp[2*h2  ][c] = pk(xnv[0], xnv[1]);
    sxnp[2*h2+1][c] = pk(xnv[2], xnv[3]);
    synp[2*h2  ][c] = pk(ynv[0], ynv[1]);
    synp[2*h2+1][c] = pk(ynv[2], ynv[3]);
    __syncthreads();

    u64 a1[2] = {0,0}, a2a[2] = {0,0}, a3[2] = {0,0}, a4[2] = {0,0};
#pragma unroll 4
    for (int c2 = 0; c2 < 64; c2++) {
        float w1v = wsa1[c2*64+c], w2v = wsa2[c2*64+c];
        float w3v = wse1[c2*64+c], w4v = wse2[c2*64+c];
        u64 w1p = pk(w1v, w1v), w2p = pk(w2v, w2v);
        u64 w3p = pk(w3v, w3v), w4p = pk(w4v, w4v);
#pragma unroll
        for (int pi = 0; pi < 2; pi++) {
            u64 yc = synp[2*h2+pi][c2], xc = sxnp[2*h2+pi][c2];
            a1[pi]  = fma2(yc, w1p, a1[pi]);
            a2a[pi] = fma2(yc, w2p, a2a[pi]);
            a3[pi]  = fma2(xc, w3p, a3[pi]);
            a4[pi]  = fma2(xc, w4p, a4[pi]);
        }
    }
    const int h = c >> 4, d = c & 15;
    const int bhh = b*Hh + h;
    const float SCq = 0.25f * 1.4426950408889634f;
#pragma unroll
    for (int pi = 0; pi < 2; pi++) {
        const int n = n0 + 4*h2 + 2*pi;
        float2 u1 = unpk(a1[pi]);   // Q rows n, n+1
        float2 u2 = unpk(a2a[pi]);  // K
        float2 u3 = unpk(a3[pi]);   // V (x1)
        size_t o0 = ((size_t)bhh*Nn + n)*Dh + d;
        g_y1[o0] = u1.x; g_y1[o0 + Dh] = u1.y;

        // pack bf16 across d with partner lane (d even <- own, d odd from c^1)
        float qx = u1.x * SCq, qy = u1.y * SCq;
        float pqx = __shfl_xor_sync(0xffffffffu, qx,   1);
        float pqy = __shfl_xor_sync(0xffffffffu, qy,   1);
        float pkx = __shfl_xor_sync(0xffffffffu, u2.x, 1);
        float pky = __shfl_xor_sync(0xffffffffu, u2.y, 1);
        float pvx = __shfl_xor_sync(0xffffffffu, u3.x, 1);
        float pvy = __shfl_xor_sync(0xffffffffu, u3.y, 1);
        if ((c & 1) == 0) {
            size_t r0 = ((size_t)bhh*Nn + n)*8 + (d >> 1);
            size_t r1 = r0 + 8;
            g_qb[r0] = cvt_bf2(pqx, qx);
            g_qb[r1] = cvt_bf2(pqy, qy);
            g_kb[r0] = cvt_bf2(pkx, u2.x);
            g_kb[r1] = cvt_bf2(pky, u2.y);
            g_vb[r0] = cvt_bf2(pvx, u3.x);
            g_vb[r1] = cvt_bf2(pvy, u3.y);
        }
    }

    // ---- channel-attn logit partials: sum over the 8 rows, atomic into g_secl
    sx1p[2*h2  ][c] = a3[0];  sx1p[2*h2+1][c] = a3[1];
    sx2p[2*h2  ][c] = a4[0];  sx2p[2*h2+1][c] = a4[1];
    __syncthreads();
#pragma unroll
    for (int e = 0; e < 8; e++) {
        int idx = t + 128*e;
        int hh = idx >> 8, ii = (idx >> 4) & 15, jj = idx & 15;
        u64 acc = 0ull;
#pragma unroll
        for (int p = 0; p < 4; p++)
            acc = fma2(sx1p[p][hh*16+ii], sx2p[p][hh*16+jj], acc);
        float2 u = unpk(acc);
        atomicAdd(&g_secl[(b*Hh + hh)*256 + ii*16 + jj], u.x + u.y);
    }
}

// ---------------- K3: flash attention, QT=128, 8 warps, double-buffered ----------------
__global__ __launch_bounds__(256) void k_flash_mma()
{
    const int qt = blockIdx.x, bh = blockIdx.y, ks = blockIdx.z;
    const int t = threadIdx.x, wid = t >> 5, lane = t & 31;
    const int g = lane >> 2, tg = lane & 3;
    const int m = lane >> 3, r8 = lane & 7;

    __shared__ __align__(16) __nv_bfloat16 sQ [QT*SKQ];
    __shared__ __align__(16) __nv_bfloat16 sK [2][KT*SKQ];
    __shared__ __align__(16) __nv_bfloat16 sV [2][KT*SKQ];

    const uint4* __restrict__ Qb4 = ((const uint4*)g_qb) + (size_t)bh*Nn*2;
    const uint4* __restrict__ Kb4 = ((const uint4*)g_kb) + (size_t)bh*Nn*2;
    const uint4* __restrict__ Vb4 = ((const uint4*)g_vb) + (size_t)bh*Nn*2;

    // Q tile: 128 rows x 32B = 256 uint4, one per thread
    {
        uint4 v = Qb4[(size_t)qt*256 + t];
        *(uint4*)(sQ + (t>>1)*SKQ + (t&1)*8) = v;
    }
    // preload tile 0: threads 0-127 load K, 128-255 load V
    {
        const int key0 = ks*KPB;
        const int tl = t & 127;
        if (t < 128) {
            uint4 kv = Kb4[(size_t)key0*2 + tl];
            *(uint4*)(sK[0] + (tl>>1)*SKQ + (tl&1)*8) = kv;
        } else {
            uint4 vv = Vb4[(size_t)key0*2 + tl];
            *(uint4*)(sV[0] + (tl>>1)*SKQ + (tl&1)*8) = vv;
        }
    }
    __syncthreads();

    const int qr = wid * 16;
    uint32_t qa0 = *(const uint32_t*)(sQ + (qr+g  )*SKQ + 2*tg);
    uint32_t qa1 = *(const uint32_t*)(sQ + (qr+g+8)*SKQ + 2*tg);
    uint32_t qa2 = *(const uint32_t*)(sQ + (qr+g  )*SKQ + 2*tg + 8);
    uint32_t qa3 = *(const uint32_t*)(sQ + (qr+g+8)*SKQ + 2*tg + 8);

    const uint32_t offK = (uint32_t)(((((m>>1)&1)*8 + r8)*SKQ + (m&1)*8) * 2);
    const uint32_t offV = (uint32_t)((((m&1)*8 + r8)*SKQ + ((m>>1)&1)*8) * 2);
    const uint32_t kb0 = smem_u32(sK[0]), kb1 = smem_u32(sK[1]);
    const uint32_t vb0 = smem_u32(sV[0]), vb1 = smem_u32(sV[1]);

    float o[2][4] = {{0,0,0,0},{0,0,0,0}};
    float lsum_lo = 0.f, lsum_hi = 0.f;

    for (int kt = 0; kt < NTIL; kt++) {
        const int cur = kt & 1;
        const bool more = (kt + 1 < NTIL);

        uint4 reg;
        if (more) {
            const int key0 = ks*KPB + (kt+1)*KT;
            const int tl = t & 127;
            reg = (t < 128) ? Kb4[(size_t)key0*2 + tl] : Vb4[(size_t)key0*2 + tl];
        }

        const uint32_t kbase = (cur ? kb1 : kb0) + offK;
        const uint32_t vbase = (cur ? vb1 : vb0) + offV;

        float s[8][4];
        uint32_t p[8][2];
#pragma unroll
        for (int kg = 0; kg < 4; kg++) {
            uint32_t b0, b1, b2, b3;
            ldsm_x4(b0, b1, b2, b3, kbase + kg*(16*SKQ*2));
            s[2*kg][0] = s[2*kg][1] = s[2*kg][2] = s[2*kg][3] = 0.f;
            s[2*kg+1][0] = s[2*kg+1][1] = s[2*kg+1][2] = s[2*kg+1][3] = 0.f;
            mma16816(s[2*kg],   qa0, qa1, qa2, qa3, b0, b1);
            mma16816(s[2*kg+1], qa0, qa1, qa2, qa3, b2, b3);
        }
        // Q pre-scaled by 0.25*log2(e) -> exp is a bare ex2
#pragma unroll
        for (int n = 0; n < 8; n++) {
            float e0 = ex2a(s[n][0]), e1 = ex2a(s[n][1]);
            float e2 = ex2a(s[n][2]), e3 = ex2a(s[n][3]);
            lsum_lo += e0 + e1;  lsum_hi += e2 + e3;
            p[n][0] = cvt_bf2(e1, e0);
            p[n][1] = cvt_bf2(e3, e2);
        }
#pragma unroll
        for (int kk = 0; kk < 4; kk++) {
            uint32_t v0, v1, v2, v3;
            ldsm_x4t(v0, v1, v2, v3, vbase + kk*(16*SKQ*2));
            mma16816(o[0], p[2*kk][0], p[2*kk][1], p[2*kk+1][0], p[2*kk+1][1], v0, v1);
            mma16816(o[1], p[2*kk][0], p[2*kk][1], p[2*kk+1][0], p[2*kk+1][1], v2, v3);
        }

        if (more) {
            const int nxt = cur ^ 1;
            const int tl = t & 127;
            if (t < 128)
                *(uint4*)(sK[nxt] + (tl>>1)*SKQ + (tl&1)*8) = reg;
            else
                *(uint4*)(sV[nxt] + (tl>>1)*SKQ + (tl&1)*8) = reg;
            __syncthreads();
        }
    }

    lsum_lo += __shfl_xor_sync(0xffffffffu, lsum_lo, 1);
    lsum_lo += __shfl_xor_sync(0xffffffffu, lsum_lo, 2);
    lsum_hi += __shfl_xor_sync(0xffffffffu, lsum_hi, 1);
    lsum_hi += __shfl_xor_sync(0xffffffffu, lsum_hi, 2);

    const int q_lo = qt*QT + qr + g;
    const int q_hi = q_lo + 8;
    float* po = g_po + ((size_t)(ks*BH + bh)*Nn)*16;
#pragma unroll
    for (int n = 0; n < 2; n++) {
        *(float2*)&po[(size_t)q_lo*16 + n*8 + 2*tg] = make_float2(o[n][0], o[n][1]);
        *(float2*)&po[(size_t)q_hi*16 + n*8 + 2*tg] = make_float2(o[n][2], o[n][3]);
    }
    if (tg == 0) {
        g_pl[(size_t)(ks*BH + bh)*Nn + q_lo] = lsum_lo;
        g_pl[(size_t)(ks*BH + bh)*Nn + q_hi] = lsum_hi;
    }
}

// ---------------- K4: secm softmax + combine + epilogue + out-proj + LN2 + MLP ----------------
__device__ __forceinline__ float leaky(float h) { return h > 0.f ? h : 0.01f * h; }

__global__ __launch_bounds__(128) void k_tail(
    const float* __restrict__ wout, const float* __restrict__ bout,
    const float* __restrict__ g2,   const float* __restrict__ be2,
    const float* __restrict__ w1,   const float* __restrict__ b1,
    const float* __restrict__ w2,   const float* __restrict__ b2,
    float* __restrict__ out)
{
    const int t = threadIdx.x;
    const int c = t & 63, h2 = t >> 6;
    const int row0 = blockIdx.x * 8;
    const int b = row0 / Nn;
    const int n0 = row0 - b*Nn;
    const int h = c >> 4, d = c & 15;
    const int bh = b*Hh + h;

    __shared__ float ssec[4][256];
    __shared__ float sq[8][64];
    __shared__ float sinvl[8][4];
    __shared__ u64 sop[4][64];
    __shared__ u64 snp[4][64];
    __shared__ u64 shp[4][256];
    __shared__ float sred[4][8];

    const float SCL = 0.25f / 144.0f;
#pragma unroll
    for (int k = 0; k < 8; k++) {
        int idx = k*128 + t;
        ssec[idx >> 8][idx & 255] = g_secl[(b*Hh + (idx >> 8))*256 + (idx & 255)];
    }
#pragma unroll
    for (int k = 0; k < 4; k++)
        sq[4*h2 + k][c] = g_y1[((size_t)bh*Nn + n0 + 4*h2 + k)*16 + d];
    if (t < 32) {
        int r = t >> 2, hh = t & 3;
        float l = 0.f;
#pragma unroll
        for (int ks = 0; ks < KSPL; ks++)
            l += g_pl[(size_t)(ks*BH + b*Hh + hh)*Nn + n0 + r];
        sinvl[r][hh] = 1.0f / l;
    }
    __syncthreads();
    if (t < 64) {
        int hh = t >> 4, ii = t & 15;
        float* row = &ssec[hh][ii*16];
        float rm = -1e30f;
#pragma unroll
        for (int j = 0; j < 16; j++) rm = fmaxf(rm, row[j]*SCL);
        float rs = 0.f;
        float ev[16];
#pragma unroll
        for (int j = 0; j < 16; j++) { ev[j] = __expf(row[j]*SCL - rm); rs += ev[j]; }
        float inv = 1.0f / rs;
#pragma unroll
        for (int j = 0; j < 16; j++) row[j] = ev[j] * inv;
    }
    __syncthreads();

    float soval[4];
#pragma unroll
    for (int k = 0; k < 4; k++) {
        int r = 4*h2 + k;
        float pv = 0.f;
#pragma unroll
        for (int ks = 0; ks < KSPL; ks++)
            pv += g_po[((size_t)(ks*BH + bh)*Nn + n0 + r)*16 + d];
        float o2 = 0.f;
#pragma unroll
        for (int i = 0; i < 16; i++)
            o2 = fmaf(sq[r][h*16 + i], ssec[h][i*16 + d], o2);
        soval[k] = pv * sinvl[r][h] * o2;
    }
    sop[2*h2  ][c] = pk(soval[0], soval[1]);
    sop[2*h2+1][c] = pk(soval[2], soval[3]);
    __syncthreads();

    u64 ac[2] = {0ull, 0ull};
#pragma unroll 4
    for (int c2 = 0; c2 < 64; c2++) {
        float w = wout[c2*64 + c];
        u64 ww = pk(w, w);
        ac[0] = fma2(ww, sop[2*h2  ][c2], ac[0]);
        ac[1] = fma2(ww, sop[2*h2+1][c2], ac[1]);
    }
    const float bo = bout[c];
    float x2v[4];
#pragma unroll
    for (int pi = 0; pi < 2; pi++) {
        float2 u = unpk(ac[pi]);
        x2v[2*pi]   = g_xt[(size_t)(row0 + 4*h2 + 2*pi    )*64 + c] + u.x + bo;
        x2v[2*pi+1] = g_xt[(size_t)(row0 + 4*h2 + 2*pi + 1)*64 + c] + u.y + bo;
    }

    const int wid = t >> 5, lane = t & 31;
#pragma unroll
    for (int k = 0; k < 4; k++) {
        float a = x2v[k], a2 = a*a;
#pragma unroll
        for (int o = 16; o > 0; o >>= 1) {
            a  += __shfl_xor_sync(0xffffffffu, a,  o);
            a2 += __shfl_xor_sync(0xffffffffu, a2, o);
        }
        if (lane == 0) { sred[wid][k*2] = a; sred[wid][k*2+1] = a2; }
    }
    __syncthreads();
    const float g2t = g2[c], be2t = be2[c];
    const int wA = 2*h2, wB = 2*h2 + 1;
    float snv[4];
#pragma unroll
    for (int k = 0; k < 4; k++) {
        float sxx = sred[wA][k*2]   + sred[wB][k*2];
        float sq2 = sred[wA][k*2+1] + sred[wB][k*2+1];
        float mm = sxx*(1.f/64.f), vv = sq2*(1.f/64.f) - mm*mm;
        snv[k] = (x2v[k]-mm)*rsqrtf(vv + 1e-5f)*g2t + be2t;
    }
    snp[2*h2  ][c] = pk(snv[0], snv[1]);
    snp[2*h2+1][c] = pk(snv[2], snv[3]);
    __syncthreads();

    u64 hh1[2][4];
#pragma unroll
    for (int kk = 0; kk < 2; kk++) {
        float bb = b1[c + 64*(h2 + 2*kk)];
#pragma unroll
        for (int p = 0; p < 4; p++) hh1[kk][p] = pk(bb, bb);
    }
#pragma unroll 2
    for (int c2 = 0; c2 < 64; c2++) {
        u64 xp[4];
#pragma unroll
        for (int p = 0; p < 4; p++) xp[p] = snp[p][c2];
#pragma unroll
        for (int kk = 0; kk < 2; kk++) {
            float w = w1[c2*256 + c + 64*(h2 + 2*kk)];
            u64 ww = pk(w, w);
#pragma unroll
            for (int p = 0; p < 4; p++)
                hh1[kk][p] = fma2(ww, xp[p], hh1[kk][p]);
        }
    }
#pragma unroll
    for (int kk = 0; kk < 2; kk++) {
#pragma unroll
        for (int p = 0; p < 4; p++) {
            float2 u = unpk(hh1[kk][p]);
            shp[p][c + 64*(h2 + 2*kk)] = pk(leaky(u.x), leaky(u.y));
        }
    }
    __syncthreads();

    u64 f[2] = {0ull, 0ull};
#pragma unroll 4
    for (int j = 0; j < 256; j++) {
        float w = w2[j*64 + c];
        u64 ww = pk(w, w);
        f[0] = fma2(ww, shp[2*h2  ][j], f[0]);
        f[1] = fma2(ww, shp[2*h2+1][j], f[1]);
    }
    const float b2t = b2[c];
#pragma unroll
    for (int pi = 0; pi < 2; pi++) {
        float2 u = unpk(f[pi]);
        float2 st = make_float2(x2v[2*pi] + u.x + b2t, x2v[2*pi+1] + u.y + b2t);
        *(float2*)&out[((size_t)b*Cc + c)*Nn + n0 + 4*h2 + 2*pi] = st;
    }
}

// ---------------- launch ----------------
extern "C" void kernel_launch(void* const* d_in, const int* in_sizes, int n_in,
                              void* d_out, int out_size)
{
    (void)in_sizes; (void)n_in; (void)out_size;
    const float* x    = (const float*)d_in[0];
    const float* y    = (const float*)d_in[1];
    const float* ln1g = (const float*)d_in[2];
    const float* ln1b = (const float*)d_in[3];
    const float* wsa1 = (const float*)d_in[4];
    const float* wsa2 = (const float*)d_in[5];
    const float* wse1 = (const float*)d_in[6];
    const float* wse2 = (const float*)d_in[7];
    const float* wout = (const float*)d_in[8];
    const float* bout = (const float*)d_in[9];
    const float* ln2g = (const float*)d_in[10];
    const float* ln2b = (const float*)d_in[11];
    const float* w1   = (const float*)d_in[12];
    const float* b1   = (const float*)d_in[13];
    const float* w2   = (const float*)d_in[14];
    const float* b2   = (const float*)d_in[15];
    float* out = (float*)d_out;

    void* secl_ptr = nullptr;
    cudaGetSymbolAddress(&secl_ptr, g_secl);
    cudaMemsetAsync(secl_ptr, 0, BH*256*sizeof(float));

    k_ln_proj<<<Bb*Nn/8, 128>>>(x, y, ln1g, ln1b, wsa1, wsa2, wse1, wse2);
    dim3 gfl(Nn/QT, BH, KSPL);
    k_flash_mma<<<gfl, 256>>>();
    k_tail<<<Bb*Nn/8, 128>>>(wout, bout, ln2g, ln2b, w1, b1, w2, b2, out);
}

// round 17
// speedup vs baseline: 1.0740x; 1.0373x over previous
#include <cuda_runtime.h>
#include <cuda_bf16.h>
#include <cstdint>

#define Bb   2
#define Cc   64
#define Nn   2304
#define Hh   4
#define Dh   16
#define BH   (Bb*Hh)
#define MLP  256

// flash-mma tiling
#define QT    128           // queries per block (8 warps x 16 rows)
#define KT    64            // keys per smem tile
#define KSPL  4             // key splits
#define KPB   (Nn/KSPL)     // 576 keys per block
#define NTIL  (KPB/KT)      // 9 tiles
#define SKQ   24            // row stride in bf16/f16 (48B, ldmatrix-friendly)

typedef unsigned long long u64;

// ---------------- scratch (device globals; no allocation) ----------------
__device__ float    g_xt [Bb*Nn*Cc];       // x transposed (b, n, c)
__device__ float    g_y1 [BH*Nn*Dh];       // Q float (for tail epilogue)
__device__ uint32_t g_qb [BH*Nn*8];        // Q bf16x2, pre-scaled by 0.25*log2e
__device__ uint32_t g_kb [BH*Nn*8];        // K bf16x2
__device__ uint32_t g_vb [BH*Nn*8];        // V f16x2
__device__ float    g_secl[BH*256];        // channel-attn logits (atomic accum)
__device__ float    g_po [KSPL*BH*Nn*16];  // unnormalized attention partials
__device__ float    g_pl [KSPL*BH*Nn];     // partial row sums

// ---------------- helpers ----------------
__device__ __forceinline__ uint32_t cvt_bf2(float hi, float lo) {
    uint32_t r; asm("cvt.rn.bf16x2.f32 %0, %1, %2;" : "=r"(r) : "f"(hi), "f"(lo)); return r;
}
__device__ __forceinline__ uint32_t cvt_h2(float hi, float lo) {
    uint32_t r; asm("cvt.rn.f16x2.f32 %0, %1, %2;" : "=r"(r) : "f"(hi), "f"(lo)); return r;
}
__device__ __forceinline__ uint32_t ex2h2(uint32_t v) {
    uint32_t r; asm("ex2.approx.f16x2 %0, %1;" : "=r"(r) : "r"(v)); return r;
}
__device__ __forceinline__ void mma16816(float d[4],
    uint32_t a0, uint32_t a1, uint32_t a2, uint32_t a3,
    uint32_t b0, uint32_t b1)
{
    asm volatile("mma.sync.aligned.m16n8k16.row.col.f32.bf16.bf16.f32 "
        "{%0,%1,%2,%3}, {%4,%5,%6,%7}, {%8,%9}, {%0,%1,%2,%3};"
        : "+f"(d[0]), "+f"(d[1]), "+f"(d[2]), "+f"(d[3])
        : "r"(a0), "r"(a1), "r"(a2), "r"(a3), "r"(b0), "r"(b1));
}
__device__ __forceinline__ void mma16816h(float d[4],
    uint32_t a0, uint32_t a1, uint32_t a2, uint32_t a3,
    uint32_t b0, uint32_t b1)
{
    asm volatile("mma.sync.aligned.m16n8k16.row.col.f32.f16.f16.f32 "
        "{%0,%1,%2,%3}, {%4,%5,%6,%7}, {%8,%9}, {%0,%1,%2,%3};"
        : "+f"(d[0]), "+f"(d[1]), "+f"(d[2]), "+f"(d[3])
        : "r"(a0), "r"(a1), "r"(a2), "r"(a3), "r"(b0), "r"(b1));
}
__device__ __forceinline__ void ldsm_x4(uint32_t& r0, uint32_t& r1, uint32_t& r2, uint32_t& r3, uint32_t addr) {
    asm volatile("ldmatrix.sync.aligned.m8n8.x4.shared.b16 {%0,%1,%2,%3}, [%4];"
        : "=r"(r0), "=r"(r1), "=r"(r2), "=r"(r3) : "r"(addr));
}
__device__ __forceinline__ void ldsm_x4t(uint32_t& r0, uint32_t& r1, uint32_t& r2, uint32_t& r3, uint32_t addr) {
    asm volatile("ldmatrix.sync.aligned.m8n8.x4.trans.shared.b16 {%0,%1,%2,%3}, [%4];"
        : "=r"(r0), "=r"(r1), "=r"(r2), "=r"(r3) : "r"(addr));
}
__device__ __forceinline__ void ldsm_x2t(uint32_t& r0, uint32_t& r1, uint32_t addr) {
    asm volatile("ldmatrix.sync.aligned.m8n8.x2.trans.shared.b16 {%0,%1}, [%2];"
        : "=r"(r0), "=r"(r1) : "r"(addr));
}
__device__ __forceinline__ u64 fma2(u64 a, u64 b, u64 c) {
    u64 d; asm("fma.rn.f32x2 %0, %1, %2, %3;" : "=l"(d) : "l"(a), "l"(b), "l"(c)); return d;
}
__device__ __forceinline__ float2 unpk(u64 v) {
    float2 r; asm("mov.b64 {%0,%1}, %2;" : "=f"(r.x), "=f"(r.y) : "l"(v)); return r;
}
__device__ __forceinline__ u64 pk(float lo, float hi) {
    u64 v; asm("mov.b64 %0, {%1,%2};" : "=l"(v) : "f"(lo), "f"(hi)); return v;
}
__device__ __forceinline__ uint32_t smem_u32(const void* p) {
    return (uint32_t)__cvta_generic_to_shared(p);
}

// ---------------- K1: transpose + LN + 4 projections + bf16/f16 QKV + secm partials ----------------
// 8 rows, 128 thr. Half h2 = t>>6 owns rows 4*h2..4*h2+3.
__global__ __launch_bounds__(128) void k_ln_proj(
    const float* __restrict__ x, const float* __restrict__ y,
    const float* __restrict__ g, const float* __restrict__ be,
    const float* __restrict__ wsa1, const float* __restrict__ wsa2,
    const float* __restrict__ wse1, const float* __restrict__ wse2)
{
    const int t = threadIdx.x;
    const int c = t & 63, h2 = t >> 6;
    const int row0 = blockIdx.x * 8;
    const int b = row0 / Nn;
    const int n0 = row0 - b*Nn;
    __shared__ u64 sxnp[4][64], synp[4][64];
    __shared__ u64 sx1p[4][64], sx2p[4][64];
    __shared__ float sred[4][16];

    float xv[4], yv[4];
#pragma unroll
    for (int k = 0; k < 4; k++) {
        int nn = n0 + 4*h2 + k;
        xv[k] = x[((size_t)b*Cc + c)*Nn + nn];
        yv[k] = y[((size_t)b*Cc + c)*Nn + nn];
        g_xt[(size_t)(row0 + 4*h2 + k)*Cc + c] = xv[k];
    }
    const int wid = t >> 5, lane = t & 31;
#pragma unroll
    for (int k = 0; k < 4; k++) {
        float a = xv[k], a2 = a*a, bb = yv[k], b2v = bb*bb;
#pragma unroll
        for (int o = 16; o > 0; o >>= 1) {
            a   += __shfl_xor_sync(0xffffffffu, a,   o);
            a2  += __shfl_xor_sync(0xffffffffu, a2,  o);
            bb  += __shfl_xor_sync(0xffffffffu, bb,  o);
            b2v += __shfl_xor_sync(0xffffffffu, b2v, o);
        }
        if (lane == 0) {
            sred[wid][k*4+0] = a;  sred[wid][k*4+1] = a2;
            sred[wid][k*4+2] = bb; sred[wid][k*4+3] = b2v;
        }
    }
    __syncthreads();
    const float gt = g[c], bet = be[c];
    float xnv[4], ynv[4];
    const int w0i = 2*h2, w1i = 2*h2 + 1;
#pragma unroll
    for (int k = 0; k < 4; k++) {
        float sx  = sred[w0i][k*4+0] + sred[w1i][k*4+0];
        float sx2 = sred[w0i][k*4+1] + sred[w1i][k*4+1];
        float sy  = sred[w0i][k*4+2] + sred[w1i][k*4+2];
        float sy2 = sred[w0i][k*4+3] + sred[w1i][k*4+3];
        float mx = sx*(1.f/64.f), vx = sx2*(1.f/64.f) - mx*mx;
        float my = sy*(1.f/64.f), vy = sy2*(1.f/64.f) - my*my;
        float rx = rsqrtf(vx + 1e-5f), ry = rsqrtf(vy + 1e-5f);
        xnv[k] = (xv[k]-mx)*rx*gt + bet;
        ynv[k] = (yv[k]-my)*ry*gt + bet;
    }
    sxnp[2*h2  ][c] = pk(xnv[0], xnv[1]);
    sxnp[2*h2+1][c] = pk(xnv[2], xnv[3]);
    synp[2*h2  ][c] = pk(ynv[0], ynv[1]);
    synp[2*h2+1][c] = pk(ynv[2], ynv[3]);
    __syncthreads();

    u64 a1[2] = {0,0}, a2a[2] = {0,0}, a3[2] = {0,0}, a4[2] = {0,0};
#pragma unroll 4
    for (int c2 = 0; c2 < 64; c2++) {
        float w1v = wsa1[c2*64+c], w2v = wsa2[c2*64+c];
        float w3v = wse1[c2*64+c], w4v = wse2[c2*64+c];
        u64 w1p = pk(w1v, w1v), w2p = pk(w2v, w2v);
        u64 w3p = pk(w3v, w3v), w4p = pk(w4v, w4v);
#pragma unroll
        for (int pi = 0; pi < 2; pi++) {
            u64 yc = synp[2*h2+pi][c2], xc = sxnp[2*h2+pi][c2];
            a1[pi]  = fma2(yc, w1p, a1[pi]);
            a2a[pi] = fma2(yc, w2p, a2a[pi]);
            a3[pi]  = fma2(xc, w3p, a3[pi]);
            a4[pi]  = fma2(xc, w4p, a4[pi]);
        }
    }
    const int h = c >> 4, d = c & 15;
    const int bhh = b*Hh + h;
    const float SCq = 0.25f * 1.4426950408889634f;
#pragma unroll
    for (int pi = 0; pi < 2; pi++) {
        const int n = n0 + 4*h2 + 2*pi;
        float2 u1 = unpk(a1[pi]);   // Q rows n, n+1
        float2 u2 = unpk(a2a[pi]);  // K
        float2 u3 = unpk(a3[pi]);   // V (x1)
        size_t o0 = ((size_t)bhh*Nn + n)*Dh + d;
        g_y1[o0] = u1.x; g_y1[o0 + Dh] = u1.y;

        // pack across d with partner lane (d even <- own, d odd from c^1)
        float qx = u1.x * SCq, qy = u1.y * SCq;
        float pqx = __shfl_xor_sync(0xffffffffu, qx,   1);
        float pqy = __shfl_xor_sync(0xffffffffu, qy,   1);
        float pkx = __shfl_xor_sync(0xffffffffu, u2.x, 1);
        float pky = __shfl_xor_sync(0xffffffffu, u2.y, 1);
        float pvx = __shfl_xor_sync(0xffffffffu, u3.x, 1);
        float pvy = __shfl_xor_sync(0xffffffffu, u3.y, 1);
        if ((c & 1) == 0) {
            size_t r0 = ((size_t)bhh*Nn + n)*8 + (d >> 1);
            size_t r1 = r0 + 8;
            g_qb[r0] = cvt_bf2(pqx, qx);
            g_qb[r1] = cvt_bf2(pqy, qy);
            g_kb[r0] = cvt_bf2(pkx, u2.x);
            g_kb[r1] = cvt_bf2(pky, u2.y);
            g_vb[r0] = cvt_h2(pvx, u3.x);      // V in f16
            g_vb[r1] = cvt_h2(pvy, u3.y);
        }
    }

    // ---- channel-attn logit partials: sum over the 8 rows, atomic into g_secl
    sx1p[2*h2  ][c] = a3[0];  sx1p[2*h2+1][c] = a3[1];
    sx2p[2*h2  ][c] = a4[0];  sx2p[2*h2+1][c] = a4[1];
    __syncthreads();
#pragma unroll
    for (int e = 0; e < 8; e++) {
        int idx = t + 128*e;
        int hh = idx >> 8, ii = (idx >> 4) & 15, jj = idx & 15;
        u64 acc = 0ull;
#pragma unroll
        for (int p = 0; p < 4; p++)
            acc = fma2(sx1p[p][hh*16+ii], sx2p[p][hh*16+jj], acc);
        float2 u = unpk(acc);
        atomicAdd(&g_secl[(b*Hh + hh)*256 + ii*16 + jj], u.x + u.y);
    }
}

// ---------------- K3: flash attention, QT=128, f16 exp/PV + ones-column rowsum ----------------
__global__ __launch_bounds__(256) void k_flash_mma()
{
    const int qt = blockIdx.x, bh = blockIdx.y, ks = blockIdx.z;
    const int t = threadIdx.x, wid = t >> 5, lane = t & 31;
    const int g = lane >> 2, tg = lane & 3;
    const int m = lane >> 3, r8 = lane & 7;

    __shared__ __align__(16) __nv_bfloat16 sQ [QT*SKQ];
    __shared__ __align__(16) __nv_bfloat16 sK [2][KT*SKQ];
    __shared__ __align__(16) __nv_bfloat16 sV [2][KT*SKQ];

    const uint4* __restrict__ Qb4 = ((const uint4*)g_qb) + (size_t)bh*Nn*2;
    const uint4* __restrict__ Kb4 = ((const uint4*)g_kb) + (size_t)bh*Nn*2;
    const uint4* __restrict__ Vb4 = ((const uint4*)g_vb) + (size_t)bh*Nn*2;

    // fill V padding cols 16-23 (both buffers) with f16 1.0 for rowsum MMA.
    // uint4 data stores only touch cols 0-15, so this persists across tiles.
    if (t < 256) {
        const uint32_t one2 = 0x3C003C00u;
        int row = t >> 2, w4 = t & 3;
        *(uint32_t*)(sV[0] + row*SKQ + 16 + w4*2) = one2;
        *(uint32_t*)(sV[1] + row*SKQ + 16 + w4*2) = one2;
    }

    // Q tile: 128 rows x 32B = 256 uint4, one per thread
    {
        uint4 v = Qb4[(size_t)qt*256 + t];
        *(uint4*)(sQ + (t>>1)*SKQ + (t&1)*8) = v;
    }
    // preload tile 0: threads 0-127 load K, 128-255 load V
    {
        const int key0 = ks*KPB;
        const int tl = t & 127;
        if (t < 128) {
            uint4 kv = Kb4[(size_t)key0*2 + tl];
            *(uint4*)(sK[0] + (tl>>1)*SKQ + (tl&1)*8) = kv;
        } else {
            uint4 vv = Vb4[(size_t)key0*2 + tl];
            *(uint4*)(sV[0] + (tl>>1)*SKQ + (tl&1)*8) = vv;
        }
    }
    __syncthreads();

    const int qr = wid * 16;
    uint32_t qa0 = *(const uint32_t*)(sQ + (qr+g  )*SKQ + 2*tg);
    uint32_t qa1 = *(const uint32_t*)(sQ + (qr+g+8)*SKQ + 2*tg);
    uint32_t qa2 = *(const uint32_t*)(sQ + (qr+g  )*SKQ + 2*tg + 8);
    uint32_t qa3 = *(const uint32_t*)(sQ + (qr+g+8)*SKQ + 2*tg + 8);

    const uint32_t offK = (uint32_t)(((((m>>1)&1)*8 + r8)*SKQ + (m&1)*8) * 2);
    const uint32_t offV = (uint32_t)((((m&1)*8 + r8)*SKQ + ((m>>1)&1)*8) * 2);
    // ones-column fragment (R14-validated): x2t uses lanes 0-15
    const uint32_t offV1 = (uint32_t)(((((lane>>3)&1)*8 + r8)*SKQ + 16) * 2);
    const uint32_t kb0 = smem_u32(sK[0]), kb1 = smem_u32(sK[1]);
    const uint32_t vb0 = smem_u32(sV[0]), vb1 = smem_u32(sV[1]);

    float o[2][4] = {{0,0,0,0},{0,0,0,0}};
    float os[4] = {0,0,0,0};   // ones-column accumulator: exact f32 row sums

    for (int kt = 0; kt < NTIL; kt++) {
        const int cur = kt & 1;
        const bool more = (kt + 1 < NTIL);

        uint4 reg;
        if (more) {
            const int key0 = ks*KPB + (kt+1)*KT;
            const int tl = t & 127;
            reg = (t < 128) ? Kb4[(size_t)key0*2 + tl] : Vb4[(size_t)key0*2 + tl];
        }

        const uint32_t kbase  = (cur ? kb1 : kb0) + offK;
        const uint32_t vbase  = (cur ? vb1 : vb0) + offV;
        const uint32_t vbase1 = (cur ? vb1 : vb0) + offV1;

        float s[8][4];
        uint32_t p[8][2];
#pragma unroll
        for (int kg = 0; kg < 4; kg++) {
            uint32_t b0, b1, b2, b3;
            ldsm_x4(b0, b1, b2, b3, kbase + kg*(16*SKQ*2));
            s[2*kg][0] = s[2*kg][1] = s[2*kg][2] = s[2*kg][3] = 0.f;
            s[2*kg+1][0] = s[2*kg+1][1] = s[2*kg+1][2] = s[2*kg+1][3] = 0.f;
            mma16816(s[2*kg],   qa0, qa1, qa2, qa3, b0, b1);
            mma16816(s[2*kg+1], qa0, qa1, qa2, qa3, b2, b3);
        }
        // Q pre-scaled by 0.25*log2(e): exp = packed f16x2 ex2
#pragma unroll
        for (int n = 0; n < 8; n++) {
            p[n][0] = ex2h2(cvt_h2(s[n][1], s[n][0]));
            p[n][1] = ex2h2(cvt_h2(s[n][3], s[n][2]));
        }
#pragma unroll
        for (int kk = 0; kk < 4; kk++) {
            uint32_t a0 = p[2*kk][0],   a1 = p[2*kk][1];
            uint32_t a2 = p[2*kk+1][0], a3 = p[2*kk+1][1];
            uint32_t v0, v1, v2, v3;
            ldsm_x4t(v0, v1, v2, v3, vbase + kk*(16*SKQ*2));
            mma16816h(o[0], a0, a1, a2, a3, v0, v1);
            mma16816h(o[1], a0, a1, a2, a3, v2, v3);
            uint32_t s0, s1;
            ldsm_x2t(s0, s1, vbase1 + kk*(16*SKQ*2));
            mma16816h(os, a0, a1, a2, a3, s0, s1);
        }

        if (more) {
            const int nxt = cur ^ 1;
            const int tl = t & 127;
            if (t < 128)
                *(uint4*)(sK[nxt] + (tl>>1)*SKQ + (tl&1)*8) = reg;
            else
                *(uint4*)(sV[nxt] + (tl>>1)*SKQ + (tl&1)*8) = reg;
            __syncthreads();
        }
    }

    const int q_lo = qt*QT + qr + g;
    const int q_hi = q_lo + 8;
    float* po = g_po + ((size_t)(ks*BH + bh)*Nn)*16;
#pragma unroll
    for (int n = 0; n < 2; n++) {
        *(float2*)&po[(size_t)q_lo*16 + n*8 + 2*tg] = make_float2(o[n][0], o[n][1]);
        *(float2*)&po[(size_t)q_hi*16 + n*8 + 2*tg] = make_float2(o[n][2], o[n][3]);
    }
    if (tg == 0) {
        g_pl[(size_t)(ks*BH + bh)*Nn + q_lo] = os[0];
        g_pl[(size_t)(ks*BH + bh)*Nn + q_hi] = os[2];
    }
}

// ---------------- K4: secm softmax + combine + epilogue + out-proj + LN2 + MLP ----------------
__device__ __forceinline__ float leaky(float h) { return h > 0.f ? h : 0.01f * h; }

__global__ __launch_bounds__(128) void k_tail(
    const float* __restrict__ wout, const float* __restrict__ bout,
    const float* __restrict__ g2,   const float* __restrict__ be2,
    const float* __restrict__ w1,   const float* __restrict__ b1,
    const float* __restrict__ w2,   const float* __restrict__ b2,
    float* __restrict__ out)
{
    const int t = threadIdx.x;
    const int c = t & 63, h2 = t >> 6;
    const int row0 = blockIdx.x * 8;
    const int b = row0 / Nn;
    const int n0 = row0 - b*Nn;
    const int h = c >> 4, d = c & 15;
    const int bh = b*Hh + h;

    __shared__ float ssec[4][256];
    __shared__ float sq[8][64];
    __shared__ float sinvl[8][4];
    __shared__ u64 sop[4][64];
    __shared__ u64 snp[4][64];
    __shared__ u64 shp[4][256];
    __shared__ float sred[4][8];

    const float SCL = 0.25f / 144.0f;
#pragma unroll
    for (int k = 0; k < 8; k++) {
        int idx = k*128 + t;
        ssec[idx >> 8][idx & 255] = g_secl[(b*Hh + (idx >> 8))*256 + (idx & 255)];
    }
#pragma unroll
    for (int k = 0; k < 4; k++)
        sq[4*h2 + k][c] = g_y1[((size_t)bh*Nn + n0 + 4*h2 + k)*16 + d];
    if (t < 32) {
        int r = t >> 2, hh = t & 3;
        float l = 0.f;
#pragma unroll
        for (int ks = 0; ks < KSPL; ks++)
            l += g_pl[(size_t)(ks*BH + b*Hh + hh)*Nn + n0 + r];
        sinvl[r][hh] = 1.0f / l;
    }
    __syncthreads();
    if (t < 64) {
        int hh = t >> 4, ii = t & 15;
        float* row = &ssec[hh][ii*16];
        float rm = -1e30f;
#pragma unroll
        for (int j = 0; j < 16; j++) rm = fmaxf(rm, row[j]*SCL);
        float rs = 0.f;
        float ev[16];
#pragma unroll
        for (int j = 0; j < 16; j++) { ev[j] = __expf(row[j]*SCL - rm); rs += ev[j]; }
        float inv = 1.0f / rs;
#pragma unroll
        for (int j = 0; j < 16; j++) row[j] = ev[j] * inv;
    }
    __syncthreads();

    float soval[4];
#pragma unroll
    for (int k = 0; k < 4; k++) {
        int r = 4*h2 + k;
        float pv = 0.f;
#pragma unroll
        for (int ks = 0; ks < KSPL; ks++)
            pv += g_po[((size_t)(ks*BH + bh)*Nn + n0 + r)*16 + d];
        float o2 = 0.f;
#pragma unroll
        for (int i = 0; i < 16; i++)
            o2 = fmaf(sq[r][h*16 + i], ssec[h][i*16 + d], o2);
        soval[k] = pv * sinvl[r][h] * o2;
    }
    sop[2*h2  ][c] = pk(soval[0], soval[1]);
    sop[2*h2+1][c] = pk(soval[2], soval[3]);
    __syncthreads();

    u64 ac[2] = {0ull, 0ull};
#pragma unroll 4
    for (int c2 = 0; c2 < 64; c2++) {
        float w = wout[c2*64 + c];
        u64 ww = pk(w, w);
        ac[0] = fma2(ww, sop[2*h2  ][c2], ac[0]);
        ac[1] = fma2(ww, sop[2*h2+1][c2], ac[1]);
    }
    const float bo = bout[c];
    float x2v[4];
#pragma unroll
    for (int pi = 0; pi < 2; pi++) {
        float2 u = unpk(ac[pi]);
        x2v[2*pi]   = g_xt[(size_t)(row0 + 4*h2 + 2*pi    )*64 + c] + u.x + bo;
        x2v[2*pi+1] = g_xt[(size_t)(row0 + 4*h2 + 2*pi + 1)*64 + c] + u.y + bo;
    }

    const int wid = t >> 5, lane = t & 31;
#pragma unroll
    for (int k = 0; k < 4; k++) {
        float a = x2v[k], a2 = a*a;
#pragma unroll
        for (int o = 16; o > 0; o >>= 1) {
            a  += __shfl_xor_sync(0xffffffffu, a,  o);
            a2 += __shfl_xor_sync(0xffffffffu, a2, o);
        }
        if (lane == 0) { sred[wid][k*2] = a; sred[wid][k*2+1] = a2; }
    }
    __syncthreads();
    const float g2t = g2[c], be2t = be2[c];
    const int wA = 2*h2, wB = 2*h2 + 1;
    float snv[4];
#pragma unroll
    for (int k = 0; k < 4; k++) {
        float sxx = sred[wA][k*2]   + sred[wB][k*2];
        float sq2 = sred[wA][k*2+1] + sred[wB][k*2+1];
        float mm = sxx*(1.f/64.f), vv = sq2*(1.f/64.f) - mm*mm;
        snv[k] = (x2v[k]-mm)*rsqrtf(vv + 1e-5f)*g2t + be2t;
    }
    snp[2*h2  ][c] = pk(snv[0], snv[1]);
    snp[2*h2+1][c] = pk(snv[2], snv[3]);
    __syncthreads();

    u64 hh1[2][4];
#pragma unroll
    for (int kk = 0; kk < 2; kk++) {
        float bb = b1[c + 64*(h2 + 2*kk)];
#pragma unroll
        for (int p = 0; p < 4; p++) hh1[kk][p] = pk(bb, bb);
    }
#pragma unroll 2
    for (int c2 = 0; c2 < 64; c2++) {
        u64 xp[4];
#pragma unroll
        for (int p = 0; p < 4; p++) xp[p] = snp[p][c2];
#pragma unroll
        for (int kk = 0; kk < 2; kk++) {
            float w = w1[c2*256 + c + 64*(h2 + 2*kk)];
            u64 ww = pk(w, w);
#pragma unroll
            for (int p = 0; p < 4; p++)
                hh1[kk][p] = fma2(ww, xp[p], hh1[kk][p]);
        }
    }
#pragma unroll
    for (int kk = 0; kk < 2; kk++) {
#pragma unroll
        for (int p = 0; p < 4; p++) {
            float2 u = unpk(hh1[kk][p]);
            shp[p][c + 64*(h2 + 2*kk)] = pk(leaky(u.x), leaky(u.y));
        }
    }
    __syncthreads();

    u64 f[2] = {0ull, 0ull};
#pragma unroll 4
    for (int j = 0; j < 256; j++) {
        float w = w2[j*64 + c];
        u64 ww = pk(w, w);
        f[0] = fma2(ww, shp[2*h2  ][j], f[0]);
        f[1] = fma2(ww, shp[2*h2+1][j], f[1]);
    }
    const float b2t = b2[c];
#pragma unroll
    for (int pi = 0; pi < 2; pi++) {
        float2 u = unpk(f[pi]);
        float2 st = make_float2(x2v[2*pi] + u.x + b2t, x2v[2*pi+1] + u.y + b2t);
        *(float2*)&out[((size_t)b*Cc + c)*Nn + n0 + 4*h2 + 2*pi] = st;
    }
}

// ---------------- launch ----------------
extern "C" void kernel_launch(void* const* d_in, const int* in_sizes, int n_in,
                              void* d_out, int out_size)
{
    (void)in_sizes; (void)n_in; (void)out_size;
    const float* x    = (const float*)d_in[0];
    const float* y    = (const float*)d_in[1];
    const float* ln1g = (const float*)d_in[2];
    const float* ln1b = (const float*)d_in[3];
    const float* wsa1 = (const float*)d_in[4];
    const float* wsa2 = (const float*)d_in[5];
    const float* wse1 = (const float*)d_in[6];
    const float* wse2 = (const float*)d_in[7];
    const float* wout = (const float*)d_in[8];
    const float* bout = (const float*)d_in[9];
    const float* ln2g = (const float*)d_in[10];
    const float* ln2b = (const float*)d_in[11];
    const float* w1   = (const float*)d_in[12];
    const float* b1   = (const float*)d_in[13];
    const float* w2   = (const float*)d_in[14];
    const float* b2   = (const float*)d_in[15];
    float* out = (float*)d_out;

    void* secl_ptr = nullptr;
    cudaGetSymbolAddress(&secl_ptr, g_secl);
    cudaMemsetAsync(secl_ptr, 0, BH*256*sizeof(float));

    k_ln_proj<<<Bb*Nn/8, 128>>>(x, y, ln1g, ln1b, wsa1, wsa2, wse1, wse2);
    dim3 gfl(Nn/QT, BH, KSPL);
    k_flash_mma<<<gfl, 256>>>();
    k_tail<<<Bb*Nn/8, 128>>>(wout, bout, ln2g, ln2b, w1, b1, w2, b2, out);
}